// round 2
// baseline (speedup 1.0000x reference)
#include <cuda_runtime.h>
#include <math.h>

#define TB 256

static const int MAXN = 500000;
static const int MAXE = 8000000;

// ---- scratch (static __device__ arrays; no allocation) ----
__device__ float2 g_degcnt[MAXN];          // {sum incoming ew, in-degree}
__device__ float  g_dinv[MAXN];            // rsqrt(deg + 1)
__device__ float4 g_xw[MAXN * 4];          // x @ W for current layer [N,16]
__device__ float4 g_sacc[MAXN * 4];        // scatter accumulator [N,16]
__device__ int    g_src[MAXE];
__device__ int    g_dst[MAXE];
__device__ float  g_enorm[MAXE];           // ew, then norm (in place)
__device__ int    g_is64;                  // 1 if edge_index buffer is int64

// softplus matching jax.nn.softplus = max(x,0) + log1p(exp(-|x|))
__device__ __forceinline__ float sp(float x) {
    return fmaxf(x, 0.0f) + log1pf(expf(-fabsf(x)));
}

__device__ __forceinline__ void red_v4(float* p, float a, float b, float c, float d) {
    asm volatile("red.global.add.v4.f32 [%0], {%1,%2,%3,%4};"
                 :: "l"(p), "f"(a), "f"(b), "f"(c), "f"(d) : "memory");
}
__device__ __forceinline__ void red_v2(float* p, float a, float b) {
    asm volatile("red.global.add.v2.f32 [%0], {%1,%2};"
                 :: "l"(p), "f"(a), "f"(b) : "memory");
}

// ---- detect edge_index dtype: int64 values < 2^31 have zero high words ----
__global__ void k_detect(const int* __restrict__ ei_raw) {
    int is64 = 1;
    for (int i = 0; i < 32; i++)
        if (ei_raw[2 * i + 1] != 0) { is64 = 0; break; }
    g_is64 = is64;
}

// ---- zero accumulators (graph replays need fresh zeros every call) ----
__global__ void k_zero(int N) {
    int n = blockIdx.x * TB + threadIdx.x;
    if (n >= N) return;
    g_degcnt[n] = make_float2(0.0f, 0.0f);
    float4 z = make_float4(0.0f, 0.0f, 0.0f, 0.0f);
#pragma unroll
    for (int k = 0; k < 4; k++) g_sacc[n * 4 + k] = z;
}

// ---- edge pass 1: index convert, edge weight, degree/count ----
__global__ void k_edge_init(const void* __restrict__ ei_raw,
                            const float* __restrict__ pos, int E) {
    int e = blockIdx.x * TB + threadIdx.x;
    if (e >= E) return;
    int s, d;
    if (g_is64) {
        const long long* ei = (const long long*)ei_raw;
        s = (int)__ldg(&ei[e]);
        d = (int)__ldg(&ei[(long long)E + e]);
    } else {
        const int* ei = (const int*)ei_raw;
        s = __ldg(&ei[e]);
        d = __ldg(&ei[E + e]);
    }
    float ax = __ldg(&pos[3 * s + 0]) - __ldg(&pos[3 * d + 0]);
    float ay = __ldg(&pos[3 * s + 1]) - __ldg(&pos[3 * d + 1]);
    float az = __ldg(&pos[3 * s + 2]) - __ldg(&pos[3 * d + 2]);
    float ew = sqrtf(ax * ax + ay * ay + az * az);
    g_src[e] = s;
    g_dst[e] = d;
    g_enorm[e] = ew;
    red_v2(&g_degcnt[d].x, ew, 1.0f);
}

// ---- node init: x0 = sp(pos@Wi + bi); xw = x0 @ W_g1 ----
__global__ void k_node_init(const float* __restrict__ pos,
                            const float* __restrict__ Wi,
                            const float* __restrict__ bi,
                            const float* __restrict__ W1, int N) {
    __shared__ float sWi[48], sbi[16], sW1[256];
    int t = threadIdx.x;
    if (t < 48) sWi[t] = Wi[t];
    if (t < 16) sbi[t] = bi[t];
    sW1[t] = W1[t];
    __syncthreads();
    int n = blockIdx.x * TB + t;
    if (n >= N) return;
    float p0 = pos[3 * n + 0], p1 = pos[3 * n + 1], p2 = pos[3 * n + 2];
    float x[16];
#pragma unroll
    for (int j = 0; j < 16; j++)
        x[j] = sp(fmaf(p0, sWi[j], fmaf(p1, sWi[16 + j], fmaf(p2, sWi[32 + j], sbi[j]))));
    float of[16];
#pragma unroll
    for (int j = 0; j < 16; j++) {
        float acc = 0.0f;
#pragma unroll
        for (int i = 0; i < 16; i++) acc = fmaf(x[i], sW1[i * 16 + j], acc);
        of[j] = acc;
    }
#pragma unroll
    for (int k = 0; k < 4; k++)
        g_xw[n * 4 + k] = make_float4(of[4 * k], of[4 * k + 1], of[4 * k + 2], of[4 * k + 3]);
}

// ---- dinv = rsqrt(deg + self-loop weight 1) ----
__global__ void k_dinv(int N) {
    int n = blockIdx.x * TB + threadIdx.x;
    if (n >= N) return;
    g_dinv[n] = rsqrtf(g_degcnt[n].x + 1.0f);
}

// ---- edge aggregation: sacc[dst] += norm * xw[src] ----
template <bool FIRST>
__global__ void k_aggregate(int E) {
    int e = blockIdx.x * TB + threadIdx.x;
    if (e >= E) return;
    int s = g_src[e];
    int d = g_dst[e];
    float nrm;
    if (FIRST) {
        nrm = __ldg(&g_dinv[s]) * g_enorm[e] * __ldg(&g_dinv[d]);
        g_enorm[e] = nrm;   // cache for layer 2
    } else {
        nrm = g_enorm[e];
    }
    const float4* xs = &g_xw[s * 4];
    float* dp = (float*)&g_sacc[d * 4];
#pragma unroll
    for (int k = 0; k < 4; k++) {
        float4 v = __ldg(&xs[k]);
        red_v4(dp + 4 * k, nrm * v.x, nrm * v.y, nrm * v.z, nrm * v.w);
    }
}

// ---- layer finalize: x = sp((sacc + dinv^2*xw)/cnt + b); xw = x @ Wnext; zero sacc ----
__global__ void k_layer_finish(const float* __restrict__ b1,
                               const float* __restrict__ W2, int N) {
    __shared__ float sb[16], sW[256];
    int t = threadIdx.x;
    if (t < 16) sb[t] = b1[t];
    sW[t] = W2[t];
    __syncthreads();
    int n = blockIdx.x * TB + t;
    if (n >= N) return;
    float dn = g_dinv[n];
    float selfw = dn * dn;
    float inv = 1.0f / (g_degcnt[n].y + 1.0f);
    float x[16];
    float4 z = make_float4(0.0f, 0.0f, 0.0f, 0.0f);
#pragma unroll
    for (int k = 0; k < 4; k++) {
        float4 sa = g_sacc[n * 4 + k];
        float4 xv = g_xw[n * 4 + k];
        x[4 * k + 0] = sp(fmaf(fmaf(selfw, xv.x, sa.x), inv, sb[4 * k + 0]));
        x[4 * k + 1] = sp(fmaf(fmaf(selfw, xv.y, sa.y), inv, sb[4 * k + 1]));
        x[4 * k + 2] = sp(fmaf(fmaf(selfw, xv.z, sa.z), inv, sb[4 * k + 2]));
        x[4 * k + 3] = sp(fmaf(fmaf(selfw, xv.w, sa.w), inv, sb[4 * k + 3]));
        g_sacc[n * 4 + k] = z;   // ready for next aggregation
    }
    float of[16];
#pragma unroll
    for (int j = 0; j < 16; j++) {
        float acc = 0.0f;
#pragma unroll
        for (int i = 0; i < 16; i++) acc = fmaf(x[i], sW[i * 16 + j], acc);
        of[j] = acc;
    }
#pragma unroll
    for (int k = 0; k < 4; k++)
        g_xw[n * 4 + k] = make_float4(of[4 * k], of[4 * k + 1], of[4 * k + 2], of[4 * k + 3]);
}

// ---- final: x2=sp(conv2); y=sp(x2@P1+bp1); sc=y@P2+bp2; out=sc/sigma ----
__global__ void k_final(const float* __restrict__ b2,
                        const float* __restrict__ Wp1,
                        const float* __restrict__ bp1,
                        const float* __restrict__ Wp2,
                        const float* __restrict__ bp2,
                        const float* __restrict__ sig,
                        float* __restrict__ out, int N) {
    __shared__ float sb2[16], sP1[256], sbp1[16], sP2[48], sbp2[3];
    int t = threadIdx.x;
    sP1[t] = Wp1[t];
    if (t < 16) { sb2[t] = b2[t]; sbp1[t] = bp1[t]; }
    if (t < 48) sP2[t] = Wp2[t];
    if (t < 3) sbp2[t] = bp2[t];
    __syncthreads();
    int n = blockIdx.x * TB + t;
    if (n >= N) return;
    float dn = g_dinv[n];
    float selfw = dn * dn;
    float inv = 1.0f / (g_degcnt[n].y + 1.0f);
    float x[16];
#pragma unroll
    for (int k = 0; k < 4; k++) {
        float4 sa = g_sacc[n * 4 + k];
        float4 xv = g_xw[n * 4 + k];
        x[4 * k + 0] = sp(fmaf(fmaf(selfw, xv.x, sa.x), inv, sb2[4 * k + 0]));
        x[4 * k + 1] = sp(fmaf(fmaf(selfw, xv.y, sa.y), inv, sb2[4 * k + 1]));
        x[4 * k + 2] = sp(fmaf(fmaf(selfw, xv.z, sa.z), inv, sb2[4 * k + 2]));
        x[4 * k + 3] = sp(fmaf(fmaf(selfw, xv.w, sa.w), inv, sb2[4 * k + 3]));
    }
    float y[16];
#pragma unroll
    for (int j = 0; j < 16; j++) {
        float acc = sbp1[j];
#pragma unroll
        for (int i = 0; i < 16; i++) acc = fmaf(x[i], sP1[i * 16 + j], acc);
        y[j] = sp(acc);
    }
    float sc[3];
#pragma unroll
    for (int j = 0; j < 3; j++) {
        float acc = sbp2[j];
#pragma unroll
        for (int i = 0; i < 16; i++) acc = fmaf(y[i], sP2[i * 3 + j], acc);
        sc[j] = acc;
    }
    float sgv = sig[n];
    out[3 * n + 0] = sc[0] / sgv;
    out[3 * n + 1] = sc[1] / sgv;
    out[3 * n + 2] = sc[2] / sgv;
}

extern "C" void kernel_launch(void* const* d_in, const int* in_sizes, int n_in,
                              void* d_out, int out_size) {
    // metadata order: pos, sigmas, edge_index, num_graphs, W_init, b_init,
    //                 W_g1, b_g1, W_g2, b_g2, W_p1, b_p1, W_p2, b_p2
    const float* pos    = (const float*)d_in[0];
    const float* sigmas = (const float*)d_in[1];
    const void*  ei     = d_in[2];
    // robust to num_graphs being present (size-1 input) or absent
    int wbase = (n_in >= 14 || (n_in > 3 && in_sizes[3] == 1)) ? 4 : 3;
    const float* W_init = (const float*)d_in[wbase + 0];
    const float* b_init = (const float*)d_in[wbase + 1];
    const float* W_g1   = (const float*)d_in[wbase + 2];
    const float* b_g1   = (const float*)d_in[wbase + 3];
    const float* W_g2   = (const float*)d_in[wbase + 4];
    const float* b_g2   = (const float*)d_in[wbase + 5];
    const float* W_p1   = (const float*)d_in[wbase + 6];
    const float* b_p1   = (const float*)d_in[wbase + 7];
    const float* W_p2   = (const float*)d_in[wbase + 8];
    const float* b_p2   = (const float*)d_in[wbase + 9];

    int N = in_sizes[0] / 3;
    if (N > MAXN) N = MAXN;
    int E = in_sizes[2] / 2;
    if (E > MAXE) E = MAXE;
    float* out = (float*)d_out;

    int nb_n = (N + TB - 1) / TB;
    int nb_e = (E + TB - 1) / TB;

    k_detect<<<1, 1>>>((const int*)ei);
    k_zero<<<nb_n, TB>>>(N);
    k_edge_init<<<nb_e, TB>>>(ei, pos, E);
    k_node_init<<<nb_n, TB>>>(pos, W_init, b_init, W_g1, N);
    k_dinv<<<nb_n, TB>>>(N);
    k_aggregate<true><<<nb_e, TB>>>(E);
    k_layer_finish<<<nb_n, TB>>>(b_g1, W_g2, N);
    k_aggregate<false><<<nb_e, TB>>>(E);
    k_final<<<nb_n, TB>>>(b_g2, W_p1, b_p1, W_p2, b_p2, sigmas, out, N);
}

// round 3
// speedup vs baseline: 1.3244x; 1.3244x over previous
#include <cuda_runtime.h>
#include <math.h>

#define TB 256
#define SCAN_B 1024

static const int MAXN = 500000;
static const int MAXE = 8000000;
static const int MAXBLK = (MAXN + SCAN_B - 1) / SCAN_B;

// ---- scratch (static __device__ arrays; no allocation) ----
__device__ float2 g_degcnt[MAXN];          // {sum incoming ew, in-degree}
__device__ float  g_dinv[MAXN];            // rsqrt(deg + 1)
__device__ float4 g_xw[MAXN * 4];          // x @ W for current layer [N,16]
__device__ float4 g_sacc[MAXN * 4];        // aggregation result [N,16]
__device__ int    g_src[MAXE];
__device__ int    g_dst[MAXE];
__device__ float  g_ew[MAXE];              // raw edge weight
__device__ int2   g_csr[MAXE];             // packed (src, norm-as-int), CSR by dst
__device__ int    g_offs[MAXN + 1];        // CSR offsets
__device__ int    g_cursor[MAXN];          // scatter cursors
__device__ int    g_blksum[MAXBLK];
__device__ int    g_is64;                  // 1 if edge_index buffer is int64

// softplus matching jax.nn.softplus = max(x,0) + log1p(exp(-|x|))
__device__ __forceinline__ float sp(float x) {
    return fmaxf(x, 0.0f) + log1pf(expf(-fabsf(x)));
}

__device__ __forceinline__ void red_v2(float* p, float a, float b) {
    asm volatile("red.global.add.v2.f32 [%0], {%1,%2};"
                 :: "l"(p), "f"(a), "f"(b) : "memory");
}

// ---- detect edge_index dtype: int64 values < 2^31 have zero high words ----
__global__ void k_detect(const int* __restrict__ ei_raw) {
    int is64 = 1;
    for (int i = 0; i < 32; i++)
        if (ei_raw[2 * i + 1] != 0) { is64 = 0; break; }
    g_is64 = is64;
}

// ---- zero per-node degree accumulators ----
__global__ void k_zero(int N) {
    int n = blockIdx.x * TB + threadIdx.x;
    if (n >= N) return;
    g_degcnt[n] = make_float2(0.0f, 0.0f);
}

// ---- edge pass 1: index convert, edge weight, degree/count ----
__global__ void k_edge_init(const void* __restrict__ ei_raw,
                            const float* __restrict__ pos, int E) {
    int e = blockIdx.x * TB + threadIdx.x;
    if (e >= E) return;
    int s, d;
    if (g_is64) {
        const long long* ei = (const long long*)ei_raw;
        s = (int)__ldg(&ei[e]);
        d = (int)__ldg(&ei[(long long)E + e]);
    } else {
        const int* ei = (const int*)ei_raw;
        s = __ldg(&ei[e]);
        d = __ldg(&ei[E + e]);
    }
    float ax = __ldg(&pos[3 * s + 0]) - __ldg(&pos[3 * d + 0]);
    float ay = __ldg(&pos[3 * s + 1]) - __ldg(&pos[3 * d + 1]);
    float az = __ldg(&pos[3 * s + 2]) - __ldg(&pos[3 * d + 2]);
    float ew = sqrtf(ax * ax + ay * ay + az * az);
    g_src[e] = s;
    g_dst[e] = d;
    g_ew[e] = ew;
    red_v2(&g_degcnt[d].x, ew, 1.0f);
}

// ---- dinv = rsqrt(deg + self-loop weight 1) ----
__global__ void k_dinv(int N) {
    int n = blockIdx.x * TB + threadIdx.x;
    if (n >= N) return;
    g_dinv[n] = rsqrtf(g_degcnt[n].x + 1.0f);
}

// ---- scan A: per-block exclusive scan of counts, record block totals ----
__global__ void k_scanA(int N) {
    __shared__ int sh[SCAN_B];
    int t = threadIdx.x;
    int i = blockIdx.x * SCAN_B + t;
    int cnt = (i < N) ? (int)g_degcnt[i].y : 0;
    sh[t] = cnt;
    __syncthreads();
    int val = cnt;
#pragma unroll
    for (int st = 1; st < SCAN_B; st <<= 1) {
        int add = (t >= st) ? sh[t - st] : 0;
        __syncthreads();
        val += add;
        sh[t] = val;
        __syncthreads();
    }
    if (i < N) g_offs[i] = val - cnt;           // exclusive, block-local
    if (t == SCAN_B - 1) g_blksum[blockIdx.x] = val;
}

// ---- scan B: single block scans block totals to exclusive prefixes ----
__global__ void k_scanB(int nblk) {
    __shared__ int sh[SCAN_B];
    int t = threadIdx.x;
    int cnt = (t < nblk) ? g_blksum[t] : 0;
    sh[t] = cnt;
    __syncthreads();
    int val = cnt;
#pragma unroll
    for (int st = 1; st < SCAN_B; st <<= 1) {
        int add = (t >= st) ? sh[t - st] : 0;
        __syncthreads();
        val += add;
        sh[t] = val;
        __syncthreads();
    }
    if (t < nblk) g_blksum[t] = val - cnt;      // exclusive
}

// ---- scan C: add block prefixes, init cursors, sentinel ----
__global__ void k_scanC(int N, int E) {
    int i = blockIdx.x * SCAN_B + threadIdx.x;
    if (i >= N) return;
    int o = g_offs[i] + g_blksum[blockIdx.x];
    g_offs[i] = o;
    g_cursor[i] = o;
    if (i == 0) g_offs[N] = E;
}

// ---- scatter: build CSR of (src, norm) sorted by dst ----
__global__ void k_scatter(int E) {
    int e = blockIdx.x * TB + threadIdx.x;
    if (e >= E) return;
    int s = g_src[e];
    int d = g_dst[e];
    float nrm = __ldg(&g_dinv[s]) * g_ew[e] * __ldg(&g_dinv[d]);
    int p = atomicAdd(&g_cursor[d], 1);
    g_csr[p] = make_int2(s, __float_as_int(nrm));
}

// ---- node init: x0 = sp(pos@Wi + bi); xw = x0 @ W_g1 ----
__global__ void k_node_init(const float* __restrict__ pos,
                            const float* __restrict__ Wi,
                            const float* __restrict__ bi,
                            const float* __restrict__ W1, int N) {
    __shared__ float sWi[48], sbi[16], sW1[256];
    int t = threadIdx.x;
    if (t < 48) sWi[t] = Wi[t];
    if (t < 16) sbi[t] = bi[t];
    sW1[t] = W1[t];
    __syncthreads();
    int n = blockIdx.x * TB + t;
    if (n >= N) return;
    float p0 = pos[3 * n + 0], p1 = pos[3 * n + 1], p2 = pos[3 * n + 2];
    float x[16];
#pragma unroll
    for (int j = 0; j < 16; j++)
        x[j] = sp(fmaf(p0, sWi[j], fmaf(p1, sWi[16 + j], fmaf(p2, sWi[32 + j], sbi[j]))));
    float of[16];
#pragma unroll
    for (int j = 0; j < 16; j++) {
        float acc = 0.0f;
#pragma unroll
        for (int i = 0; i < 16; i++) acc = fmaf(x[i], sW1[i * 16 + j], acc);
        of[j] = acc;
    }
#pragma unroll
    for (int k = 0; k < 4; k++)
        g_xw[n * 4 + k] = make_float4(of[4 * k], of[4 * k + 1], of[4 * k + 2], of[4 * k + 3]);
}

// ---- gather aggregation: sacc[n] = sum over incoming edges of norm * xw[src]
//      4 threads per node; thread k handles features [4k, 4k+4) ----
__global__ void k_agg(int N) {
    int tid = blockIdx.x * TB + threadIdx.x;
    int n = tid >> 2;
    int k = tid & 3;
    if (n >= N) return;
    int e = g_offs[n];
    int end = g_offs[n + 1];
    float4 acc = make_float4(0.0f, 0.0f, 0.0f, 0.0f);
    for (; e < end; e++) {
        int2 pk = __ldg(&g_csr[e]);
        float nrm = __int_as_float(pk.y);
        float4 v = __ldg(&g_xw[pk.x * 4 + k]);
        acc.x = fmaf(nrm, v.x, acc.x);
        acc.y = fmaf(nrm, v.y, acc.y);
        acc.z = fmaf(nrm, v.z, acc.z);
        acc.w = fmaf(nrm, v.w, acc.w);
    }
    g_sacc[n * 4 + k] = acc;
}

// ---- layer finalize: x = sp((sacc + dinv^2*xw)/cnt + b); xw = x @ Wnext ----
__global__ void k_layer_finish(const float* __restrict__ b1,
                               const float* __restrict__ W2, int N) {
    __shared__ float sb[16], sW[256];
    int t = threadIdx.x;
    if (t < 16) sb[t] = b1[t];
    sW[t] = W2[t];
    __syncthreads();
    int n = blockIdx.x * TB + t;
    if (n >= N) return;
    float dn = g_dinv[n];
    float selfw = dn * dn;
    float inv = 1.0f / (g_degcnt[n].y + 1.0f);
    float x[16];
#pragma unroll
    for (int k = 0; k < 4; k++) {
        float4 sa = g_sacc[n * 4 + k];
        float4 xv = g_xw[n * 4 + k];
        x[4 * k + 0] = sp(fmaf(fmaf(selfw, xv.x, sa.x), inv, sb[4 * k + 0]));
        x[4 * k + 1] = sp(fmaf(fmaf(selfw, xv.y, sa.y), inv, sb[4 * k + 1]));
        x[4 * k + 2] = sp(fmaf(fmaf(selfw, xv.z, sa.z), inv, sb[4 * k + 2]));
        x[4 * k + 3] = sp(fmaf(fmaf(selfw, xv.w, sa.w), inv, sb[4 * k + 3]));
    }
    float of[16];
#pragma unroll
    for (int j = 0; j < 16; j++) {
        float acc = 0.0f;
#pragma unroll
        for (int i = 0; i < 16; i++) acc = fmaf(x[i], sW[i * 16 + j], acc);
        of[j] = acc;
    }
#pragma unroll
    for (int k = 0; k < 4; k++)
        g_xw[n * 4 + k] = make_float4(of[4 * k], of[4 * k + 1], of[4 * k + 2], of[4 * k + 3]);
}

// ---- final: x2=sp(conv2); y=sp(x2@P1+bp1); sc=y@P2+bp2; out=sc/sigma ----
__global__ void k_final(const float* __restrict__ b2,
                        const float* __restrict__ Wp1,
                        const float* __restrict__ bp1,
                        const float* __restrict__ Wp2,
                        const float* __restrict__ bp2,
                        const float* __restrict__ sig,
                        float* __restrict__ out, int N) {
    __shared__ float sb2[16], sP1[256], sbp1[16], sP2[48], sbp2[3];
    int t = threadIdx.x;
    sP1[t] = Wp1[t];
    if (t < 16) { sb2[t] = b2[t]; sbp1[t] = bp1[t]; }
    if (t < 48) sP2[t] = Wp2[t];
    if (t < 3) sbp2[t] = bp2[t];
    __syncthreads();
    int n = blockIdx.x * TB + t;
    if (n >= N) return;
    float dn = g_dinv[n];
    float selfw = dn * dn;
    float inv = 1.0f / (g_degcnt[n].y + 1.0f);
    float x[16];
#pragma unroll
    for (int k = 0; k < 4; k++) {
        float4 sa = g_sacc[n * 4 + k];
        float4 xv = g_xw[n * 4 + k];
        x[4 * k + 0] = sp(fmaf(fmaf(selfw, xv.x, sa.x), inv, sb2[4 * k + 0]));
        x[4 * k + 1] = sp(fmaf(fmaf(selfw, xv.y, sa.y), inv, sb2[4 * k + 1]));
        x[4 * k + 2] = sp(fmaf(fmaf(selfw, xv.z, sa.z), inv, sb2[4 * k + 2]));
        x[4 * k + 3] = sp(fmaf(fmaf(selfw, xv.w, sa.w), inv, sb2[4 * k + 3]));
    }
    float y[16];
#pragma unroll
    for (int j = 0; j < 16; j++) {
        float acc = sbp1[j];
#pragma unroll
        for (int i = 0; i < 16; i++) acc = fmaf(x[i], sP1[i * 16 + j], acc);
        y[j] = sp(acc);
    }
    float sc[3];
#pragma unroll
    for (int j = 0; j < 3; j++) {
        float acc = sbp2[j];
#pragma unroll
        for (int i = 0; i < 16; i++) acc = fmaf(y[i], sP2[i * 3 + j], acc);
        sc[j] = acc;
    }
    float sgv = sig[n];
    out[3 * n + 0] = sc[0] / sgv;
    out[3 * n + 1] = sc[1] / sgv;
    out[3 * n + 2] = sc[2] / sgv;
}

extern "C" void kernel_launch(void* const* d_in, const int* in_sizes, int n_in,
                              void* d_out, int out_size) {
    // metadata order: pos, sigmas, edge_index, num_graphs, W_init, b_init,
    //                 W_g1, b_g1, W_g2, b_g2, W_p1, b_p1, W_p2, b_p2
    const float* pos    = (const float*)d_in[0];
    const float* sigmas = (const float*)d_in[1];
    const void*  ei     = d_in[2];
    int wbase = (n_in >= 14 || (n_in > 3 && in_sizes[3] == 1)) ? 4 : 3;
    const float* W_init = (const float*)d_in[wbase + 0];
    const float* b_init = (const float*)d_in[wbase + 1];
    const float* W_g1   = (const float*)d_in[wbase + 2];
    const float* b_g1   = (const float*)d_in[wbase + 3];
    const float* W_g2   = (const float*)d_in[wbase + 4];
    const float* b_g2   = (const float*)d_in[wbase + 5];
    const float* W_p1   = (const float*)d_in[wbase + 6];
    const float* b_p1   = (const float*)d_in[wbase + 7];
    const float* W_p2   = (const float*)d_in[wbase + 8];
    const float* b_p2   = (const float*)d_in[wbase + 9];

    int N = in_sizes[0] / 3;
    if (N > MAXN) N = MAXN;
    int E = in_sizes[2] / 2;
    if (E > MAXE) E = MAXE;
    float* out = (float*)d_out;

    int nb_n = (N + TB - 1) / TB;
    int nb_e = (E + TB - 1) / TB;
    int nb_s = (N + SCAN_B - 1) / SCAN_B;
    int nb_a = (4 * N + TB - 1) / TB;

    k_detect<<<1, 1>>>((const int*)ei);
    k_zero<<<nb_n, TB>>>(N);
    k_edge_init<<<nb_e, TB>>>(ei, pos, E);
    k_node_init<<<nb_n, TB>>>(pos, W_init, b_init, W_g1, N);
    k_dinv<<<nb_n, TB>>>(N);
    // build CSR (counting sort by dst)
    k_scanA<<<nb_s, SCAN_B>>>(N);
    k_scanB<<<1, SCAN_B>>>(nb_s);
    k_scanC<<<nb_s, SCAN_B>>>(N, E);
    k_scatter<<<nb_e, TB>>>(E);
    // layer 1
    k_agg<<<nb_a, TB>>>(N);
    k_layer_finish<<<nb_n, TB>>>(b_g1, W_g2, N);
    // layer 2
    k_agg<<<nb_a, TB>>>(N);
    k_final<<<nb_n, TB>>>(b_g2, W_p1, b_p1, W_p2, b_p2, sigmas, out, N);
}

// round 4
// speedup vs baseline: 1.5116x; 1.1414x over previous
#include <cuda_runtime.h>
#include <cuda_fp16.h>
#include <math.h>

#define TB 256
#define SCAN_B 1024

static const int MAXN = 500000;
static const int MAXE = 8000000;
static const int MAXBLK = (MAXN + SCAN_B - 1) / SCAN_B;

// ---- scratch (static __device__ arrays; no allocation) ----
__device__ float2 g_degcnt[MAXN];          // {sum incoming ew, in-degree}
__device__ float  g_dinv[MAXN];            // rsqrt(deg + 1)
__device__ uint2  g_xwh[MAXN * 4];         // x @ W, fp16: thread k of node n holds feats 4k..4k+3
__device__ int    g_src[MAXE];
__device__ int    g_dst[MAXE];
__device__ float  g_ew[MAXE];              // raw edge weight
__device__ int2   g_csr[MAXE];             // packed (src, norm-as-int), CSR by dst
__device__ int    g_offs[MAXN + 1];        // CSR offsets
__device__ int    g_cursor[MAXN];          // scatter cursors
__device__ int    g_blksum[MAXBLK];
__device__ int    g_is64;

// softplus matching jax.nn.softplus = max(x,0) + log1p(exp(-|x|))
__device__ __forceinline__ float sp(float x) {
    return fmaxf(x, 0.0f) + log1pf(expf(-fabsf(x)));
}

__device__ __forceinline__ void red_v2(float* p, float a, float b) {
    asm volatile("red.global.add.v2.f32 [%0], {%1,%2};"
                 :: "l"(p), "f"(a), "f"(b) : "memory");
}

__device__ __forceinline__ uint2 pack4h(float a, float b, float c, float d) {
    __half2 h0 = __floats2half2_rn(a, b);
    __half2 h1 = __floats2half2_rn(c, d);
    uint2 u;
    u.x = *(unsigned*)&h0;
    u.y = *(unsigned*)&h1;
    return u;
}

__device__ __forceinline__ float4 unpack4h(uint2 u) {
    __half2 h0 = *(__half2*)&u.x;
    __half2 h1 = *(__half2*)&u.y;
    float2 f0 = __half22float2(h0);
    float2 f1 = __half22float2(h1);
    return make_float4(f0.x, f0.y, f1.x, f1.y);
}

// ---- detect edge_index dtype ----
__global__ void k_detect(const int* __restrict__ ei_raw) {
    int is64 = 1;
    for (int i = 0; i < 32; i++)
        if (ei_raw[2 * i + 1] != 0) { is64 = 0; break; }
    g_is64 = is64;
}

__global__ void k_zero(int N) {
    int n = blockIdx.x * TB + threadIdx.x;
    if (n >= N) return;
    g_degcnt[n] = make_float2(0.0f, 0.0f);
}

// ---- edge pass 1: index convert, edge weight, degree/count ----
__global__ void k_edge_init(const void* __restrict__ ei_raw,
                            const float* __restrict__ pos, int E) {
    int e = blockIdx.x * TB + threadIdx.x;
    if (e >= E) return;
    int s, d;
    if (g_is64) {
        const long long* ei = (const long long*)ei_raw;
        s = (int)__ldg(&ei[e]);
        d = (int)__ldg(&ei[(long long)E + e]);
    } else {
        const int* ei = (const int*)ei_raw;
        s = __ldg(&ei[e]);
        d = __ldg(&ei[E + e]);
    }
    float ax = __ldg(&pos[3 * s + 0]) - __ldg(&pos[3 * d + 0]);
    float ay = __ldg(&pos[3 * s + 1]) - __ldg(&pos[3 * d + 1]);
    float az = __ldg(&pos[3 * s + 2]) - __ldg(&pos[3 * d + 2]);
    float ew = sqrtf(ax * ax + ay * ay + az * az);
    g_src[e] = s;
    g_dst[e] = d;
    g_ew[e] = ew;
    red_v2(&g_degcnt[d].x, ew, 1.0f);
}

// ---- scan A: per-block exclusive scan of counts + dinv ----
__global__ void k_scanA(int N) {
    __shared__ int sh[SCAN_B];
    int t = threadIdx.x;
    int i = blockIdx.x * SCAN_B + t;
    int cnt = 0;
    if (i < N) {
        float2 dc = g_degcnt[i];
        cnt = (int)dc.y;
        g_dinv[i] = rsqrtf(dc.x + 1.0f);
    }
    sh[t] = cnt;
    __syncthreads();
    int val = cnt;
#pragma unroll
    for (int st = 1; st < SCAN_B; st <<= 1) {
        int add = (t >= st) ? sh[t - st] : 0;
        __syncthreads();
        val += add;
        sh[t] = val;
        __syncthreads();
    }
    if (i < N) g_offs[i] = val - cnt;
    if (t == SCAN_B - 1) g_blksum[blockIdx.x] = val;
}

__global__ void k_scanB(int nblk) {
    __shared__ int sh[SCAN_B];
    int t = threadIdx.x;
    int cnt = (t < nblk) ? g_blksum[t] : 0;
    sh[t] = cnt;
    __syncthreads();
    int val = cnt;
#pragma unroll
    for (int st = 1; st < SCAN_B; st <<= 1) {
        int add = (t >= st) ? sh[t - st] : 0;
        __syncthreads();
        val += add;
        sh[t] = val;
        __syncthreads();
    }
    if (t < nblk) g_blksum[t] = val - cnt;
}

__global__ void k_scanC(int N, int E) {
    int i = blockIdx.x * SCAN_B + threadIdx.x;
    if (i >= N) return;
    int o = g_offs[i] + g_blksum[blockIdx.x];
    g_offs[i] = o;
    g_cursor[i] = o;
    if (i == 0) g_offs[N] = E;
}

// ---- scatter: build CSR of (src, norm) sorted by dst ----
__global__ void k_scatter(int E) {
    int e = blockIdx.x * TB + threadIdx.x;
    if (e >= E) return;
    int s = g_src[e];
    int d = g_dst[e];
    float nrm = __ldg(&g_dinv[s]) * g_ew[e] * __ldg(&g_dinv[d]);
    int p = atomicAdd(&g_cursor[d], 1);
    g_csr[p] = make_int2(s, __float_as_int(nrm));
}

// ---- node init: x0 = sp(pos@Wi + bi); xw = x0 @ W_g1 (fp16) ----
__global__ void k_node_init(const float* __restrict__ pos,
                            const float* __restrict__ Wi,
                            const float* __restrict__ bi,
                            const float* __restrict__ W1, int N) {
    __shared__ float sWi[48], sbi[16], sW1[256];
    int t = threadIdx.x;
    if (t < 48) sWi[t] = Wi[t];
    if (t < 16) sbi[t] = bi[t];
    sW1[t] = W1[t];
    __syncthreads();
    int n = blockIdx.x * TB + t;
    if (n >= N) return;
    float p0 = pos[3 * n + 0], p1 = pos[3 * n + 1], p2 = pos[3 * n + 2];
    float x[16];
#pragma unroll
    for (int j = 0; j < 16; j++)
        x[j] = sp(fmaf(p0, sWi[j], fmaf(p1, sWi[16 + j], fmaf(p2, sWi[32 + j], sbi[j]))));
    float of[16];
#pragma unroll
    for (int j = 0; j < 16; j++) {
        float acc = 0.0f;
#pragma unroll
        for (int i = 0; i < 16; i++) acc = fmaf(x[i], sW1[i * 16 + j], acc);
        of[j] = acc;
    }
#pragma unroll
    for (int k = 0; k < 4; k++)
        g_xwh[n * 4 + k] = pack4h(of[4 * k], of[4 * k + 1], of[4 * k + 2], of[4 * k + 3]);
}

// ---- common: aggregate + GCN finalize (quad of threads per node) ----
// Returns finalized x[4k..4k+3] = sp((agg + dinv^2*xw_self)/cnt + b)
__device__ __forceinline__ float4 agg_finalize(int n, int k, const float* sb) {
    int e = g_offs[n];
    int end = g_offs[n + 1];
    float4 acc = make_float4(0.0f, 0.0f, 0.0f, 0.0f);
#pragma unroll 2
    for (; e < end; e++) {
        int2 pk = __ldg(&g_csr[e]);
        float nrm = __int_as_float(pk.y);
        float4 v = unpack4h(__ldg(&g_xwh[pk.x * 4 + k]));
        acc.x = fmaf(nrm, v.x, acc.x);
        acc.y = fmaf(nrm, v.y, acc.y);
        acc.z = fmaf(nrm, v.z, acc.z);
        acc.w = fmaf(nrm, v.w, acc.w);
    }
    float dn = __ldg(&g_dinv[n]);
    float selfw = dn * dn;
    float inv = 1.0f / (g_degcnt[n].y + 1.0f);
    float4 xs = unpack4h(g_xwh[n * 4 + k]);
    float4 x;
    x.x = sp(fmaf(fmaf(selfw, xs.x, acc.x), inv, sb[4 * k + 0]));
    x.y = sp(fmaf(fmaf(selfw, xs.y, acc.y), inv, sb[4 * k + 1]));
    x.z = sp(fmaf(fmaf(selfw, xs.z, acc.z), inv, sb[4 * k + 2]));
    x.w = sp(fmaf(fmaf(selfw, xs.w, acc.w), inv, sb[4 * k + 3]));
    return x;
}

// quad 16x16 matmul: x distributed 4 feats/thread -> o distributed 4/thread
__device__ __forceinline__ void quad_matmul(float4 x, const float* sW, int k,
                                            unsigned mask, int qbase, float o[4]) {
    o[0] = o[1] = o[2] = o[3] = 0.0f;
#pragma unroll
    for (int q = 0; q < 4; q++) {
        float4 xq;
        xq.x = __shfl_sync(mask, x.x, qbase + q, 32);
        xq.y = __shfl_sync(mask, x.y, qbase + q, 32);
        xq.z = __shfl_sync(mask, x.z, qbase + q, 32);
        xq.w = __shfl_sync(mask, x.w, qbase + q, 32);
        const float* w0 = &sW[(4 * q + 0) * 16 + 4 * k];
        const float* w1 = &sW[(4 * q + 1) * 16 + 4 * k];
        const float* w2 = &sW[(4 * q + 2) * 16 + 4 * k];
        const float* w3 = &sW[(4 * q + 3) * 16 + 4 * k];
#pragma unroll
        for (int j = 0; j < 4; j++) {
            o[j] = fmaf(xq.x, w0[j], o[j]);
            o[j] = fmaf(xq.y, w1[j], o[j]);
            o[j] = fmaf(xq.z, w2[j], o[j]);
            o[j] = fmaf(xq.w, w3[j], o[j]);
        }
    }
}

// ---- layer 1: aggregate + finalize + matmul W_g2 -> xwh ----
__global__ void k_agg1(const float* __restrict__ b1,
                       const float* __restrict__ W2, int N) {
    __shared__ float sb[16], sW[256];
    int t = threadIdx.x;
    if (t < 16) sb[t] = b1[t];
    sW[t] = W2[t];
    __syncthreads();
    int tid = blockIdx.x * TB + t;
    int n = tid >> 2;
    int k = tid & 3;
    if (n >= N) return;
    int lane = t & 31;
    int qbase = lane & ~3;
    unsigned mask = 0xFu << qbase;
    float4 x = agg_finalize(n, k, sb);
    float o[4];
    quad_matmul(x, sW, k, mask, qbase, o);
    g_xwh[n * 4 + k] = pack4h(o[0], o[1], o[2], o[3]);
}

// ---- layer 2: aggregate + finalize + MLP (P1,sp,P2) + /sigma -> out ----
__global__ void k_agg2(const float* __restrict__ b2,
                       const float* __restrict__ Wp1,
                       const float* __restrict__ bp1,
                       const float* __restrict__ Wp2,
                       const float* __restrict__ bp2,
                       const float* __restrict__ sig,
                       float* __restrict__ out, int N) {
    __shared__ float sb2[16], sP1[256], sbp1[16], sP2[48], sbp2[3];
    int t = threadIdx.x;
    sP1[t] = Wp1[t];
    if (t < 16) { sb2[t] = b2[t]; sbp1[t] = bp1[t]; }
    if (t < 48) sP2[t] = Wp2[t];
    if (t < 3) sbp2[t] = bp2[t];
    __syncthreads();
    int tid = blockIdx.x * TB + t;
    int n = tid >> 2;
    int k = tid & 3;
    if (n >= N) return;
    int lane = t & 31;
    int qbase = lane & ~3;
    unsigned mask = 0xFu << qbase;
    float4 x = agg_finalize(n, k, sb2);
    float o[4];
    quad_matmul(x, sP1, k, mask, qbase, o);
    float4 y;
    y.x = sp(o[0] + sbp1[4 * k + 0]);
    y.y = sp(o[1] + sbp1[4 * k + 1]);
    y.z = sp(o[2] + sbp1[4 * k + 2]);
    y.w = sp(o[3] + sbp1[4 * k + 3]);
    // partial sc over this thread's 4 features
    float sc[3];
#pragma unroll
    for (int j = 0; j < 3; j++) {
        sc[j] = y.x * sP2[(4 * k + 0) * 3 + j]
              + y.y * sP2[(4 * k + 1) * 3 + j]
              + y.z * sP2[(4 * k + 2) * 3 + j]
              + y.w * sP2[(4 * k + 3) * 3 + j];
    }
    // quad reduce
#pragma unroll
    for (int j = 0; j < 3; j++) {
        sc[j] += __shfl_xor_sync(mask, sc[j], 1, 32);
        sc[j] += __shfl_xor_sync(mask, sc[j], 2, 32);
    }
    if (k == 0) {
        float sgv = __ldg(&sig[n]);
        out[3 * n + 0] = (sc[0] + sbp2[0]) / sgv;
        out[3 * n + 1] = (sc[1] + sbp2[1]) / sgv;
        out[3 * n + 2] = (sc[2] + sbp2[2]) / sgv;
    }
}

extern "C" void kernel_launch(void* const* d_in, const int* in_sizes, int n_in,
                              void* d_out, int out_size) {
    const float* pos    = (const float*)d_in[0];
    const float* sigmas = (const float*)d_in[1];
    const void*  ei     = d_in[2];
    int wbase = (n_in >= 14 || (n_in > 3 && in_sizes[3] == 1)) ? 4 : 3;
    const float* W_init = (const float*)d_in[wbase + 0];
    const float* b_init = (const float*)d_in[wbase + 1];
    const float* W_g1   = (const float*)d_in[wbase + 2];
    const float* b_g1   = (const float*)d_in[wbase + 3];
    const float* W_g2   = (const float*)d_in[wbase + 4];
    const float* b_g2   = (const float*)d_in[wbase + 5];
    const float* W_p1   = (const float*)d_in[wbase + 6];
    const float* b_p1   = (const float*)d_in[wbase + 7];
    const float* W_p2   = (const float*)d_in[wbase + 8];
    const float* b_p2   = (const float*)d_in[wbase + 9];

    int N = in_sizes[0] / 3;
    if (N > MAXN) N = MAXN;
    int E = in_sizes[2] / 2;
    if (E > MAXE) E = MAXE;
    float* out = (float*)d_out;

    int nb_n = (N + TB - 1) / TB;
    int nb_e = (E + TB - 1) / TB;
    int nb_s = (N + SCAN_B - 1) / SCAN_B;
    int nb_a = (4 * N + TB - 1) / TB;

    k_detect<<<1, 1>>>((const int*)ei);
    k_zero<<<nb_n, TB>>>(N);
    k_edge_init<<<nb_e, TB>>>(ei, pos, E);
    k_node_init<<<nb_n, TB>>>(pos, W_init, b_init, W_g1, N);
    k_scanA<<<nb_s, SCAN_B>>>(N);
    k_scanB<<<1, SCAN_B>>>(nb_s);
    k_scanC<<<nb_s, SCAN_B>>>(N, E);
    k_scatter<<<nb_e, TB>>>(E);
    k_agg1<<<nb_a, TB>>>(b_g1, W_g2, N);
    k_agg2<<<nb_a, TB>>>(b_g2, W_p1, b_p1, W_p2, b_p2, sigmas, out, N);
}